// round 2
// baseline (speedup 1.0000x reference)
#include <cuda_runtime.h>
#include <math_constants.h>

#define F_DIM 128
#define A_DIM_C 256
#define BM 256            // rows per block
#define WM 32             // rows per warp
#define NCH 64            // n-chunk width
#define LDX 132           // padded smem stride (floats)
#define RPB 1024          // rows per pooling block

// scratch (device globals — no allocation allowed)
__device__ float g_A[1 << 20];        // per-row score, then exp
__device__ float g_segmax[8192];
__device__ float g_segsum[8192];

__device__ __forceinline__ unsigned f2tf(float f) {
    unsigned r;
    asm("cvt.rna.tf32.f32 %0, %1;" : "=r"(r) : "f"(f));
    return r;
}
__device__ __forceinline__ float tanh_ap(float x) {
    float y;
    asm("tanh.approx.f32 %0, %1;" : "=f"(y) : "f"(x));
    return y;
}
__device__ __forceinline__ void mma_tf32(float c[4], const unsigned a[4],
                                         unsigned b0, unsigned b1) {
    asm volatile(
        "mma.sync.aligned.m16n8k8.row.col.f32.tf32.tf32.f32 "
        "{%0,%1,%2,%3},{%4,%5,%6,%7},{%8,%9},{%0,%1,%2,%3};\n"
        : "+f"(c[0]), "+f"(c[1]), "+f"(c[2]), "+f"(c[3])
        : "r"(a[0]), "r"(a[1]), "r"(a[2]), "r"(a[3]), "r"(b0), "r"(b1));
}

// ---------------------------------------------------------------------------
// Kernel 1: fused gated-attention score:  A[i] = ww . (tanh(xVw^T+Vb) * sig(xUw^T+Ub)) + wb
// ---------------------------------------------------------------------------
__global__ void __launch_bounds__(256, 1)
score_kernel(const float* __restrict__ x,
             const float* __restrict__ Vw, const float* __restrict__ Vb,
             const float* __restrict__ Uw, const float* __restrict__ Ub,
             const float* __restrict__ ww, const float* __restrict__ wb,
             int N)
{
    extern __shared__ float sm[];
    float* xs = sm;                       // BM*LDX
    float* vs = xs + BM * LDX;            // NCH*LDX
    float* us = vs + NCH * LDX;           // NCH*LDX
    float* sp = us + NCH * LDX;           // 768: Vb | Ub | ww

    const int tid  = threadIdx.x;
    const int warp = tid >> 5;
    const int lane = tid & 31;
    const int qid  = lane >> 2;           // 0..7
    const int tq   = lane & 3;            // 0..3
    const int row0 = blockIdx.x * BM;

    // load x tile (tf32-rounded), zero-fill past N
    for (int i = tid; i < BM * (F_DIM / 4); i += 256) {
        int r  = i >> 5;                  // F_DIM/4 == 32
        int c4 = i & 31;
        float4 v = make_float4(0.f, 0.f, 0.f, 0.f);
        if (row0 + r < N)
            v = *reinterpret_cast<const float4*>(x + (size_t)(row0 + r) * F_DIM + c4 * 4);
        float* dst = xs + r * LDX + c4 * 4;
        dst[0] = __uint_as_float(f2tf(v.x));
        dst[1] = __uint_as_float(f2tf(v.y));
        dst[2] = __uint_as_float(f2tf(v.z));
        dst[3] = __uint_as_float(f2tf(v.w));
    }
    sp[tid]       = Vb[tid];
    sp[256 + tid] = Ub[tid];
    sp[512 + tid] = ww[tid];
    __syncthreads();

    float s00 = 0.f, s01 = 0.f, s10 = 0.f, s11 = 0.f;
    const float* xw = xs + warp * WM * LDX;

    for (int ch = 0; ch < A_DIM_C / NCH; ch++) {
        if (ch) __syncthreads();
        // load weight chunk (tf32-rounded)
        const float* Vg = Vw + (size_t)ch * NCH * F_DIM;
        const float* Ug = Uw + (size_t)ch * NCH * F_DIM;
        for (int i = tid; i < NCH * (F_DIM / 4); i += 256) {
            int r  = i >> 5;
            int c4 = i & 31;
            float4 v = *reinterpret_cast<const float4*>(Vg + r * F_DIM + c4 * 4);
            float4 u = *reinterpret_cast<const float4*>(Ug + r * F_DIM + c4 * 4);
            float* dv = vs + r * LDX + c4 * 4;
            float* du = us + r * LDX + c4 * 4;
            dv[0] = __uint_as_float(f2tf(v.x)); dv[1] = __uint_as_float(f2tf(v.y));
            dv[2] = __uint_as_float(f2tf(v.z)); dv[3] = __uint_as_float(f2tf(v.w));
            du[0] = __uint_as_float(f2tf(u.x)); du[1] = __uint_as_float(f2tf(u.y));
            du[2] = __uint_as_float(f2tf(u.z)); du[3] = __uint_as_float(f2tf(u.w));
        }
        __syncthreads();

        float accV[2][8][4];
        float accU[2][8][4];
#pragma unroll
        for (int t = 0; t < 2; t++)
#pragma unroll
            for (int nt = 0; nt < 8; nt++)
#pragma unroll
                for (int p = 0; p < 4; p++) { accV[t][nt][p] = 0.f; accU[t][nt][p] = 0.f; }

#pragma unroll
        for (int ks = 0; ks < 16; ks++) {
            unsigned a[2][4];
#pragma unroll
            for (int t = 0; t < 2; t++) {
                const float* ap = xw + (t * 16 + qid) * LDX + ks * 8 + tq;
                a[t][0] = __float_as_uint(ap[0]);
                a[t][1] = __float_as_uint(ap[8 * LDX]);
                a[t][2] = __float_as_uint(ap[4]);
                a[t][3] = __float_as_uint(ap[8 * LDX + 4]);
            }
#pragma unroll
            for (int nt = 0; nt < 8; nt++) {
                const float* bp = vs + (nt * 8 + qid) * LDX + ks * 8 + tq;
                unsigned b0 = __float_as_uint(bp[0]);
                unsigned b1 = __float_as_uint(bp[4]);
                mma_tf32(accV[0][nt], a[0], b0, b1);
                mma_tf32(accV[1][nt], a[1], b0, b1);
                const float* cp = us + (nt * 8 + qid) * LDX + ks * 8 + tq;
                unsigned d0 = __float_as_uint(cp[0]);
                unsigned d1 = __float_as_uint(cp[4]);
                mma_tf32(accU[0][nt], a[0], d0, d1);
                mma_tf32(accU[1][nt], a[1], d0, d1);
            }
        }

        // epilogue: bias + tanh*sigmoid gate + ww dot (partial)
        int nb = ch * NCH;
#pragma unroll
        for (int t = 0; t < 2; t++)
#pragma unroll
            for (int nt = 0; nt < 8; nt++)
#pragma unroll
                for (int p = 0; p < 4; p++) {
                    int n = nb + nt * 8 + tq * 2 + (p & 1);
                    float v = accV[t][nt][p] + sp[n];
                    float u = accU[t][nt][p] + sp[256 + n];
                    float g = tanh_ap(v) * (0.5f + 0.5f * tanh_ap(0.5f * u));
                    float c = sp[512 + n] * g;
                    if (t == 0) { if (p < 2) s00 += c; else s01 += c; }
                    else        { if (p < 2) s10 += c; else s11 += c; }
                }
    }

    // reduce across the 4 threads of each quad (lane%4)
#pragma unroll
    for (int o = 1; o < 4; o <<= 1) {
        s00 += __shfl_xor_sync(0xffffffffu, s00, o);
        s01 += __shfl_xor_sync(0xffffffffu, s01, o);
        s10 += __shfl_xor_sync(0xffffffffu, s10, o);
        s11 += __shfl_xor_sync(0xffffffffu, s11, o);
    }
    if (tq == 0) {
        float wbv = wb[0];
        int rb = row0 + warp * WM + qid;
        if (rb      < N) g_A[rb]      = s00 + wbv;
        if (rb + 8  < N) g_A[rb + 8]  = s01 + wbv;
        if (rb + 16 < N) g_A[rb + 16] = s10 + wbv;
        if (rb + 24 < N) g_A[rb + 24] = s11 + wbv;
    }
}

// ---------------------------------------------------------------------------
// Kernel 2: init output + segment stats
// ---------------------------------------------------------------------------
__global__ void init_kernel(float* __restrict__ out, int bf, int B) {
    int i = blockIdx.x * blockDim.x + threadIdx.x;
    if (i < bf) out[i] = 0.f;
    if (i < B) { g_segmax[i] = -CUDART_INF_F; g_segsum[i] = 0.f; }
}

// ---------------------------------------------------------------------------
// Kernel 3: segment max (atomic float-max via int/uint ordering trick)
// ---------------------------------------------------------------------------
__global__ void segmax_kernel(const int* __restrict__ seg, int N) {
    int i = blockIdx.x * blockDim.x + threadIdx.x;
    if (i >= N) return;
    float v = g_A[i];
    float* a = &g_segmax[seg[i]];
    if (v >= 0.f) atomicMax((int*)a, __float_as_int(v));
    else          atomicMin((unsigned int*)a, __float_as_uint(v));
}

// ---------------------------------------------------------------------------
// Kernel 4: exp + segment sum
// ---------------------------------------------------------------------------
__global__ void exps_kernel(const int* __restrict__ seg, int N) {
    int i = blockIdx.x * blockDim.x + threadIdx.x;
    if (i >= N) return;
    int s = seg[i];
    float e = expf(g_A[i] - g_segmax[s]);
    g_A[i] = e;
    atomicAdd(&g_segsum[s], e);
}

// ---------------------------------------------------------------------------
// Kernel 5: weighted segment-sum pooling (indices sorted -> run-length flush)
// ---------------------------------------------------------------------------
__global__ void __launch_bounds__(128)
pool_kernel(const float* __restrict__ x, const int* __restrict__ seg,
            float* __restrict__ out, int N)
{
    __shared__ int   ss[RPB];
    __shared__ float wA[RPB];
    int r0 = blockIdx.x * RPB;
    if (r0 >= N) return;
    int cnt = min(RPB, N - r0);

    for (int r = threadIdx.x; r < cnt; r += 128) {
        int s = seg[r0 + r];
        ss[r] = s;
        wA[r] = g_A[r0 + r] / (g_segsum[s] + 1e-9f);
    }
    __syncthreads();

    const int t = threadIdx.x;
    float acc = 0.f;
    int cur = ss[0];
#pragma unroll 4
    for (int r = 0; r < cnt; r++) {
        int s = ss[r];
        if (s != cur) {
            atomicAdd(out + (size_t)cur * F_DIM + t, acc);
            acc = 0.f;
            cur = s;
        }
        acc += wA[r] * x[(size_t)(r0 + r) * F_DIM + t];
    }
    atomicAdd(out + (size_t)cur * F_DIM + t, acc);
}

// ---------------------------------------------------------------------------
extern "C" void kernel_launch(void* const* d_in, const int* in_sizes, int n_in,
                              void* d_out, int out_size)
{
    const float* x   = (const float*)d_in[0];
    const int*   seg = (const int*)d_in[1];
    int base = (n_in >= 9) ? 3 : 2;   // d_in[2] is the batch_size scalar when present
    const float* Vw = (const float*)d_in[base + 0];
    const float* Vb = (const float*)d_in[base + 1];
    const float* Uw = (const float*)d_in[base + 2];
    const float* Ub = (const float*)d_in[base + 3];
    const float* ww = (const float*)d_in[base + 4];
    const float* wb = (const float*)d_in[base + 5];

    int N = in_sizes[0] / F_DIM;
    int B = out_size / F_DIM;
    float* out = (float*)d_out;

    const size_t SMEM = (size_t)(BM * LDX + 2 * NCH * LDX + 768) * sizeof(float);
    cudaFuncSetAttribute(score_kernel, cudaFuncAttributeMaxDynamicSharedMemorySize, (int)SMEM);

    int nb1 = (N + BM - 1) / BM;
    score_kernel<<<nb1, 256, SMEM>>>(x, Vw, Vb, Uw, Ub, ww, wb, N);

    init_kernel<<<(out_size + 255) / 256, 256>>>(out, out_size, B);
    segmax_kernel<<<(N + 255) / 256, 256>>>(seg, N);
    exps_kernel<<<(N + 255) / 256, 256>>>(seg, N);
    pool_kernel<<<(N + RPB - 1) / RPB, 128>>>(x, seg, out, N);
}

// round 4
// speedup vs baseline: 1.9987x; 1.9987x over previous
#include <cuda_runtime.h>
#include <cuda_fp16.h>
#include <math_constants.h>
#include <cstdint>

#define F_DIM 128
#define BM    256      // rows per score block
#define NCH   32       // a-dim chunk per iteration (V and U each)
#define RPB   512      // rows per pooling block

// device-global scratch (no allocation allowed)
__device__ float  g_A[1 << 20];
__device__ float  g_segsum[8192];
__device__ __half g_wf[512 * 128];     // fp16 weights: rows 0-255 = Vw, 256-511 = Uw
__device__ float4 g_tab[256];          // {Vb, Ub, ww, 0} per a-dim

// ---------------------------------------------------------------------------
__device__ __forceinline__ uint32_t smem_u32(const void* p) {
    uint32_t a;
    asm("{ .reg .u64 t; cvta.to.shared.u64 t, %1; cvt.u32.u64 %0, t; }" : "=r"(a) : "l"(p));
    return a;
}
__device__ __forceinline__ float tanh_ap(float x) {
    float y; asm("tanh.approx.f32 %0, %1;" : "=f"(y) : "f"(x)); return y;
}
__device__ __forceinline__ void ldsm4(uint32_t* r, uint32_t a) {
    asm volatile("ldmatrix.sync.aligned.m8n8.x4.shared.b16 {%0,%1,%2,%3}, [%4];"
                 : "=r"(r[0]), "=r"(r[1]), "=r"(r[2]), "=r"(r[3]) : "r"(a));
}
__device__ __forceinline__ void mma16816(float* c, const uint32_t* a, uint32_t b0, uint32_t b1) {
    asm volatile("mma.sync.aligned.m16n8k16.row.col.f32.f16.f16.f32 "
                 "{%0,%1,%2,%3},{%4,%5,%6,%7},{%8,%9},{%0,%1,%2,%3};"
                 : "+f"(c[0]), "+f"(c[1]), "+f"(c[2]), "+f"(c[3])
                 : "r"(a[0]), "r"(a[1]), "r"(a[2]), "r"(a[3]), "r"(b0), "r"(b1));
}
__device__ __forceinline__ void cpa16(uint32_t dst, const void* src) {
    asm volatile("cp.async.cg.shared.global [%0], [%1], 16;" :: "r"(dst), "l"(src));
}
__device__ __forceinline__ void cpa_commit() { asm volatile("cp.async.commit_group;"); }
__device__ __forceinline__ void cpa_wait0()  { asm volatile("cp.async.wait_group 0;"); }

// smem layout constants (bytes)
#define XS_OFF   0            // x tile: 256 rows x 256B (128 fp16) swizzled = 64KB
#define WS_OFF   65536        // weights: 2 bufs x (64 rows x 256B) = 32KB
#define WS_SZ    16384
#define TAB_OFF  98304        // 256 x float4 = 4KB
#define SMEM_SZ  102400

// ---------------------------------------------------------------------------
// Kernel 0: one-time weight conversion + table build
// ---------------------------------------------------------------------------
__global__ void prep_kernel(const float* __restrict__ Vw, const float* __restrict__ Vb,
                            const float* __restrict__ Uw, const float* __restrict__ Ub,
                            const float* __restrict__ ww) {
    int i = blockIdx.x * blockDim.x + threadIdx.x;
    if (i < 32768) {
        g_wf[i]         = __float2half(Vw[i]);
        g_wf[32768 + i] = __float2half(Uw[i]);
    }
    if (i < 256) g_tab[i] = make_float4(Vb[i], Ub[i], ww[i], 0.f);
}

// ---------------------------------------------------------------------------
// Kernel 1: fused score + exp + segment-sum.  fp16 mma.sync + ldmatrix.
// ---------------------------------------------------------------------------
__global__ void __launch_bounds__(256, 2)
score_kernel(const float* __restrict__ x, const int* __restrict__ seg,
             const float* __restrict__ wb, int N)
{
    extern __shared__ char sm[];
    const uint32_t sb  = smem_u32(sm);
    const uint32_t xsb = sb + XS_OFF;
    const uint32_t wsb = sb + WS_OFF;
    float4* tab = reinterpret_cast<float4*>(sm + TAB_OFF);

    const int tid  = threadIdx.x;
    const int warp = tid >> 5;
    const int lane = tid & 31;
    const int lh   = lane >> 4;        // k-half selector for ldmatrix
    const int l15  = lane & 15;
    const long row0 = (long)blockIdx.x * BM;

    // table -> smem
    tab[tid] = g_tab[tid];

    // prefetch weights chunk 0 into buffer 0 (cp.async, 16B granules)
    {
#pragma unroll
        for (int j = 0; j < 4; j++) {
            int i = tid + j * 256;
            int r = i >> 4, c16 = i & 15;
            int n = (r < 32) ? r : 256 + (r - 32);     // chunk 0: local rows map directly
            cpa16(wsb + r * 256 + (((c16 ^ (r & 7)) << 4)),
                  g_wf + (size_t)n * 128 + c16 * 8);
        }
        cpa_commit();
    }

    // load x tile (f32 -> fp16, swizzled)
#pragma unroll 4
    for (int i = tid; i < 4096; i += 256) {
        int r = i >> 4, c16 = i & 15;
        long gr = row0 + r;
        float4 v0 = make_float4(0.f, 0.f, 0.f, 0.f), v1 = v0;
        if (gr < N) {
            const float4* gp = reinterpret_cast<const float4*>(x + gr * 128 + c16 * 8);
            v0 = gp[0]; v1 = gp[1];
        }
        uint4 o;
        o.x = __half2_raw(__floats2half2_rn(v0.x, v0.y)).x | ((uint32_t)__half2_raw(__floats2half2_rn(v0.x, v0.y)).y << 16);
        // (use packed conversion properly below)
        __half2 h0 = __floats2half2_rn(v0.x, v0.y);
        __half2 h1 = __floats2half2_rn(v0.z, v0.w);
        __half2 h2 = __floats2half2_rn(v1.x, v1.y);
        __half2 h3 = __floats2half2_rn(v1.z, v1.w);
        o.x = *reinterpret_cast<uint32_t*>(&h0);
        o.y = *reinterpret_cast<uint32_t*>(&h1);
        o.z = *reinterpret_cast<uint32_t*>(&h2);
        o.w = *reinterpret_cast<uint32_t*>(&h3);
        *reinterpret_cast<uint4*>(sm + XS_OFF + r * 256 + (((c16 ^ (r & 7)) << 4))) = o;
    }
    cpa_wait0();
    __syncthreads();

    // per-thread fragment row bases (byte offsets); swizzle xor = lane&7 for all
    const uint32_t rbA0 = xsb + (uint32_t)(warp * 32 + l15) * 256;       // m-tile 0
    const uint32_t rbA1 = rbA0 + 16 * 256;                               // m-tile 1
    // B rows: V local rows 0-31, U rows 32-63 (per buffer)
    const uint32_t rbV0 = wsb + (uint32_t)l15 * 256;
    const uint32_t rbV1 = rbV0 + 16 * 256;
    const uint32_t rbU0 = rbV0 + 32 * 256;
    const uint32_t rbU1 = rbV1 + 32 * 256;

    float s[2][2] = {{0.f, 0.f}, {0.f, 0.f}};   // per-thread row partials [mt][rowhalf]

    for (int ci = 0; ci < 8; ci++) {
        const int b = ci & 1;
        const uint32_t wofs = (uint32_t)b * WS_SZ;

        // prefetch next chunk into the other buffer
        if (ci < 7) {
            const int nb2 = (ci + 1) * 32;
            const uint32_t dofs = (uint32_t)(b ^ 1) * WS_SZ;
#pragma unroll
            for (int j = 0; j < 4; j++) {
                int i = tid + j * 256;
                int r = i >> 4, c16 = i & 15;
                int n = (r < 32) ? nb2 + r : 256 + nb2 + (r - 32);
                cpa16(wsb + dofs + r * 256 + (((c16 ^ (r & 7)) << 4)),
                      g_wf + (size_t)n * 128 + c16 * 8);
            }
            cpa_commit();
        }

        float accV[2][4][4], accU[2][4][4];
#pragma unroll
        for (int mt = 0; mt < 2; mt++)
#pragma unroll
            for (int nt = 0; nt < 4; nt++)
#pragma unroll
                for (int p = 0; p < 4; p++) { accV[mt][nt][p] = 0.f; accU[mt][nt][p] = 0.f; }

#pragma unroll
        for (int ks = 0; ks < 8; ks++) {
            const uint32_t coff = (uint32_t)(((2 * ks + lh) ^ (lane & 7)) << 4);
            uint32_t a0[4], a1[4], bv0[4], bv1[4], bu0[4], bu1[4];
            ldsm4(a0,  rbA0 + coff);
            ldsm4(a1,  rbA1 + coff);
            ldsm4(bv0, rbV0 + wofs + coff);
            ldsm4(bv1, rbV1 + wofs + coff);
            ldsm4(bu0, rbU0 + wofs + coff);
            ldsm4(bu1, rbU1 + wofs + coff);
            // n-tiles: 0,1 from group0; 2,3 from group1
            mma16816(accV[0][0], a0, bv0[0], bv0[2]);
            mma16816(accV[0][1], a0, bv0[1], bv0[3]);
            mma16816(accV[0][2], a0, bv1[0], bv1[2]);
            mma16816(accV[0][3], a0, bv1[1], bv1[3]);
            mma16816(accV[1][0], a1, bv0[0], bv0[2]);
            mma16816(accV[1][1], a1, bv0[1], bv0[3]);
            mma16816(accV[1][2], a1, bv1[0], bv1[2]);
            mma16816(accV[1][3], a1, bv1[1], bv1[3]);
            mma16816(accU[0][0], a0, bu0[0], bu0[2]);
            mma16816(accU[0][1], a0, bu0[1], bu0[3]);
            mma16816(accU[0][2], a0, bu1[0], bu1[2]);
            mma16816(accU[0][3], a0, bu1[1], bu1[3]);
            mma16816(accU[1][0], a1, bu0[0], bu0[2]);
            mma16816(accU[1][1], a1, bu0[1], bu0[3]);
            mma16816(accU[1][2], a1, bu1[0], bu1[2]);
            mma16816(accU[1][3], a1, bu1[1], bu1[3]);
        }

        // epilogue: bias + tanh*sigmoid gate + ww weight, accumulate per row
        const float4* tb = tab + ci * 32;
#pragma unroll
        for (int mt = 0; mt < 2; mt++)
#pragma unroll
            for (int nt = 0; nt < 4; nt++)
#pragma unroll
                for (int p2 = 0; p2 < 2; p2++) {
                    const int nl = nt * 8 + (lane & 3) * 2 + p2;
                    const float4 pr = tb[nl];
#pragma unroll
                    for (int h = 0; h < 2; h++) {       // rowhalf: regs p2 / p2+2
                        const int p = p2 + 2 * h;
                        float v = accV[mt][nt][p] + pr.x;
                        float u = accU[mt][nt][p] + pr.y;
                        float g = tanh_ap(v) * (0.5f + 0.5f * tanh_ap(0.5f * u));
                        s[mt][h] += g * pr.z;
                    }
                }

        if (ci < 7) { cpa_wait0(); __syncthreads(); }
    }

    // reduce across the 4 threads sharing each row
#pragma unroll
    for (int mt = 0; mt < 2; mt++)
#pragma unroll
        for (int h = 0; h < 2; h++) {
            s[mt][h] += __shfl_xor_sync(0xffffffffu, s[mt][h], 1);
            s[mt][h] += __shfl_xor_sync(0xffffffffu, s[mt][h], 2);
        }
    if ((lane & 3) == 0) {
        const float wbv = wb[0];
#pragma unroll
        for (int mt = 0; mt < 2; mt++)
#pragma unroll
            for (int h = 0; h < 2; h++) {
                long row = row0 + warp * 32 + mt * 16 + (lane >> 2) + 8 * h;
                if (row < N) {
                    float e = expf(s[mt][h] + wbv);
                    g_A[row] = e;
                    atomicAdd(&g_segsum[seg[row]], e);
                }
            }
    }
}

// ---------------------------------------------------------------------------
// Kernel 2: zero output + segment sums
// ---------------------------------------------------------------------------
__global__ void init_kernel(float* __restrict__ out, int bf, int B) {
    int i = blockIdx.x * blockDim.x + threadIdx.x;
    if (i < bf) out[i] = 0.f;
    if (i < B) g_segsum[i] = 0.f;
}

// ---------------------------------------------------------------------------
// Kernel 3: weighted segment-sum pooling (indices sorted -> run-length flush)
// ---------------------------------------------------------------------------
__global__ void __launch_bounds__(128)
pool_kernel(const float* __restrict__ x, const int* __restrict__ seg,
            float* __restrict__ out, int N)
{
    __shared__ int   ss[RPB];
    __shared__ float wA[RPB];
    int r0 = blockIdx.x * RPB;
    if (r0 >= N) return;
    int cnt = min(RPB, N - r0);

    for (int r = threadIdx.x; r < cnt; r += 128) {
        int sgi = seg[r0 + r];
        ss[r] = sgi;
        wA[r] = g_A[r0 + r] / (g_segsum[sgi] + 1e-9f);
    }
    __syncthreads();

    const int t = threadIdx.x;
    float acc = 0.f;
    int cur = ss[0];
#pragma unroll 4
    for (int r = 0; r < cnt; r++) {
        int sgi = ss[r];
        if (sgi != cur) {
            atomicAdd(out + (size_t)cur * F_DIM + t, acc);
            acc = 0.f;
            cur = sgi;
        }
        acc += wA[r] * x[(size_t)(r0 + r) * F_DIM + t];
    }
    atomicAdd(out + (size_t)cur * F_DIM + t, acc);
}

// ---------------------------------------------------------------------------
extern "C" void kernel_launch(void* const* d_in, const int* in_sizes, int n_in,
                              void* d_out, int out_size)
{
    const float* x   = (const float*)d_in[0];
    const int*   seg = (const int*)d_in[1];
    int base = (n_in >= 9) ? 3 : 2;
    const float* Vw = (const float*)d_in[base + 0];
    const float* Vb = (const float*)d_in[base + 1];
    const float* Uw = (const float*)d_in[base + 2];
    const float* Ub = (const float*)d_in[base + 3];
    const float* ww = (const float*)d_in[base + 4];
    const float* wb = (const float*)d_in[base + 5];

    int N = in_sizes[0] / F_DIM;
    int B = out_size / F_DIM;
    float* out = (float*)d_out;

    cudaFuncSetAttribute(score_kernel, cudaFuncAttributeMaxDynamicSharedMemorySize, SMEM_SZ);

    prep_kernel<<<128, 256>>>(Vw, Vb, Uw, Ub, ww);
    init_kernel<<<(out_size + 255) / 256, 256>>>(out, out_size, B);
    score_kernel<<<(N + BM - 1) / BM, 256, SMEM_SZ>>>(x, seg, wb, N);
    pool_kernel<<<(N + RPB - 1) / RPB, 128>>>(x, seg, out, N);
}

// round 5
// speedup vs baseline: 2.5485x; 1.2751x over previous
#include <cuda_runtime.h>
#include <cuda_fp16.h>
#include <math_constants.h>
#include <cstdint>

#define F_DIM 128
#define BM    256      // rows per score block
#define RPB   256      // rows per pooling block
#define PTHR  256      // pooling threads (2 row-groups of 128)

// device-global scratch (no allocation allowed)
__device__ float  g_A[1 << 20];
__device__ float  g_segsum[8192];
__device__ __half g_wf[512 * 128];     // fp16 weights: rows 0-255 = Vw, 256-511 = Uw
__device__ float4 g_tab[256];          // {Vb, Ub, ww, 0} per a-dim

// ---------------------------------------------------------------------------
__device__ __forceinline__ uint32_t smem_u32(const void* p) {
    uint32_t a;
    asm("{ .reg .u64 t; cvta.to.shared.u64 t, %1; cvt.u32.u64 %0, t; }" : "=r"(a) : "l"(p));
    return a;
}
__device__ __forceinline__ float tanh_ap(float x) {
    float y; asm("tanh.approx.f32 %0, %1;" : "=f"(y) : "f"(x)); return y;
}
__device__ __forceinline__ void ldsm4(uint32_t* r, uint32_t a) {
    asm volatile("ldmatrix.sync.aligned.m8n8.x4.shared.b16 {%0,%1,%2,%3}, [%4];"
                 : "=r"(r[0]), "=r"(r[1]), "=r"(r[2]), "=r"(r[3]) : "r"(a));
}
__device__ __forceinline__ void mma16816(float* c, const uint32_t* a, uint32_t b0, uint32_t b1) {
    asm volatile("mma.sync.aligned.m16n8k16.row.col.f32.f16.f16.f32 "
                 "{%0,%1,%2,%3},{%4,%5,%6,%7},{%8,%9},{%0,%1,%2,%3};"
                 : "+f"(c[0]), "+f"(c[1]), "+f"(c[2]), "+f"(c[3])
                 : "r"(a[0]), "r"(a[1]), "r"(a[2]), "r"(a[3]), "r"(b0), "r"(b1));
}
__device__ __forceinline__ void cpa16(uint32_t dst, const void* src) {
    asm volatile("cp.async.cg.shared.global [%0], [%1], 16;" :: "r"(dst), "l"(src));
}
__device__ __forceinline__ void cpa_commit() { asm volatile("cp.async.commit_group;"); }
__device__ __forceinline__ void cpa_wait0()  { asm volatile("cp.async.wait_group 0;"); }

// smem layout constants (bytes)
#define XS_OFF   0            // x tile: 256 rows x 256B (128 fp16) swizzled = 64KB
#define WS_OFF   65536        // weights: 2 bufs x (64 rows x 256B) = 32KB
#define WS_SZ    16384
#define TAB_OFF  98304        // 256 x float4 = 4KB
#define SMEM_SZ  102400

// ---------------------------------------------------------------------------
// Kernel 0: one-time weight conversion + table build
// ---------------------------------------------------------------------------
__global__ void prep_kernel(const float* __restrict__ Vw, const float* __restrict__ Vb,
                            const float* __restrict__ Uw, const float* __restrict__ Ub,
                            const float* __restrict__ ww) {
    int i = blockIdx.x * blockDim.x + threadIdx.x;
    if (i < 32768) {
        g_wf[i]         = __float2half(Vw[i]);
        g_wf[32768 + i] = __float2half(Uw[i]);
    }
    if (i < 256) g_tab[i] = make_float4(Vb[i], Ub[i], ww[i], 0.f);
}

// ---------------------------------------------------------------------------
// Kernel 1: fused score + exp + segment-sum.  fp16 mma.sync + ldmatrix.
// ---------------------------------------------------------------------------
__global__ void __launch_bounds__(256, 2)
score_kernel(const float* __restrict__ x, const int* __restrict__ seg,
             const float* __restrict__ wb, int N)
{
    extern __shared__ char sm[];
    const uint32_t sb  = smem_u32(sm);
    const uint32_t xsb = sb + XS_OFF;
    const uint32_t wsb = sb + WS_OFF;
    float4* tab = reinterpret_cast<float4*>(sm + TAB_OFF);

    const int tid  = threadIdx.x;
    const int warp = tid >> 5;
    const int lane = tid & 31;
    const int lh   = lane >> 4;        // k-half selector for ldmatrix
    const int l15  = lane & 15;
    const long row0 = (long)blockIdx.x * BM;

    // table -> smem
    tab[tid] = g_tab[tid];

    // prefetch weights chunk 0 into buffer 0 (cp.async, 16B granules)
    {
#pragma unroll
        for (int j = 0; j < 4; j++) {
            int i = tid + j * 256;
            int r = i >> 4, c16 = i & 15;
            int n = (r < 32) ? r : 256 + (r - 32);     // chunk 0: local rows map directly
            cpa16(wsb + r * 256 + (((c16 ^ (r & 7)) << 4)),
                  g_wf + (size_t)n * 128 + c16 * 8);
        }
        cpa_commit();
    }

    // load x tile (f32 -> fp16, swizzled)
#pragma unroll 4
    for (int i = tid; i < 4096; i += 256) {
        int r = i >> 4, c16 = i & 15;
        long gr = row0 + r;
        float4 v0 = make_float4(0.f, 0.f, 0.f, 0.f), v1 = v0;
        if (gr < N) {
            const float4* gp = reinterpret_cast<const float4*>(x + gr * 128 + c16 * 8);
            v0 = gp[0]; v1 = gp[1];
        }
        __half2 h0 = __floats2half2_rn(v0.x, v0.y);
        __half2 h1 = __floats2half2_rn(v0.z, v0.w);
        __half2 h2 = __floats2half2_rn(v1.x, v1.y);
        __half2 h3 = __floats2half2_rn(v1.z, v1.w);
        uint4 o;
        o.x = *reinterpret_cast<uint32_t*>(&h0);
        o.y = *reinterpret_cast<uint32_t*>(&h1);
        o.z = *reinterpret_cast<uint32_t*>(&h2);
        o.w = *reinterpret_cast<uint32_t*>(&h3);
        *reinterpret_cast<uint4*>(sm + XS_OFF + r * 256 + (((c16 ^ (r & 7)) << 4))) = o;
    }
    cpa_wait0();
    __syncthreads();

    // per-thread fragment row bases (byte offsets); swizzle xor = lane&7 for all
    const uint32_t rbA0 = xsb + (uint32_t)(warp * 32 + l15) * 256;       // m-tile 0
    const uint32_t rbA1 = rbA0 + 16 * 256;                               // m-tile 1
    // B rows: V local rows 0-31, U rows 32-63 (per buffer)
    const uint32_t rbV0 = wsb + (uint32_t)l15 * 256;
    const uint32_t rbV1 = rbV0 + 16 * 256;
    const uint32_t rbU0 = rbV0 + 32 * 256;
    const uint32_t rbU1 = rbV1 + 32 * 256;

    float s[2][2] = {{0.f, 0.f}, {0.f, 0.f}};   // per-thread row partials [mt][rowhalf]

    for (int ci = 0; ci < 8; ci++) {
        const int b = ci & 1;
        const uint32_t wofs = (uint32_t)b * WS_SZ;

        // prefetch next chunk into the other buffer
        if (ci < 7) {
            const int nb2 = (ci + 1) * 32;
            const uint32_t dofs = (uint32_t)(b ^ 1) * WS_SZ;
#pragma unroll
            for (int j = 0; j < 4; j++) {
                int i = tid + j * 256;
                int r = i >> 4, c16 = i & 15;
                int n = (r < 32) ? nb2 + r : 256 + nb2 + (r - 32);
                cpa16(wsb + dofs + r * 256 + (((c16 ^ (r & 7)) << 4)),
                      g_wf + (size_t)n * 128 + c16 * 8);
            }
            cpa_commit();
        }

        float accV[2][4][4], accU[2][4][4];
#pragma unroll
        for (int mt = 0; mt < 2; mt++)
#pragma unroll
            for (int nt = 0; nt < 4; nt++)
#pragma unroll
                for (int p = 0; p < 4; p++) { accV[mt][nt][p] = 0.f; accU[mt][nt][p] = 0.f; }

#pragma unroll
        for (int ks = 0; ks < 8; ks++) {
            const uint32_t coff = (uint32_t)(((2 * ks + lh) ^ (lane & 7)) << 4);
            uint32_t a0[4], a1[4], bv0[4], bv1[4], bu0[4], bu1[4];
            ldsm4(a0,  rbA0 + coff);
            ldsm4(a1,  rbA1 + coff);
            ldsm4(bv0, rbV0 + wofs + coff);
            ldsm4(bv1, rbV1 + wofs + coff);
            ldsm4(bu0, rbU0 + wofs + coff);
            ldsm4(bu1, rbU1 + wofs + coff);
            mma16816(accV[0][0], a0, bv0[0], bv0[2]);
            mma16816(accV[0][1], a0, bv0[1], bv0[3]);
            mma16816(accV[0][2], a0, bv1[0], bv1[2]);
            mma16816(accV[0][3], a0, bv1[1], bv1[3]);
            mma16816(accV[1][0], a1, bv0[0], bv0[2]);
            mma16816(accV[1][1], a1, bv0[1], bv0[3]);
            mma16816(accV[1][2], a1, bv1[0], bv1[2]);
            mma16816(accV[1][3], a1, bv1[1], bv1[3]);
            mma16816(accU[0][0], a0, bu0[0], bu0[2]);
            mma16816(accU[0][1], a0, bu0[1], bu0[3]);
            mma16816(accU[0][2], a0, bu1[0], bu1[2]);
            mma16816(accU[0][3], a0, bu1[1], bu1[3]);
            mma16816(accU[1][0], a1, bu0[0], bu0[2]);
            mma16816(accU[1][1], a1, bu0[1], bu0[3]);
            mma16816(accU[1][2], a1, bu1[0], bu1[2]);
            mma16816(accU[1][3], a1, bu1[1], bu1[3]);
        }

        // epilogue: bias + tanh*sigmoid gate + ww weight, accumulate per row
        const float4* tb = tab + ci * 32;
#pragma unroll
        for (int mt = 0; mt < 2; mt++)
#pragma unroll
            for (int nt = 0; nt < 4; nt++)
#pragma unroll
                for (int p2 = 0; p2 < 2; p2++) {
                    const int nl = nt * 8 + (lane & 3) * 2 + p2;
                    const float4 pr = tb[nl];
#pragma unroll
                    for (int h = 0; h < 2; h++) {       // rowhalf: regs p2 / p2+2
                        const int p = p2 + 2 * h;
                        float v = accV[mt][nt][p] + pr.x;
                        float u = accU[mt][nt][p] + pr.y;
                        float g = tanh_ap(v) * (0.5f + 0.5f * tanh_ap(0.5f * u));
                        s[mt][h] += g * pr.z;
                    }
                }

        if (ci < 7) { cpa_wait0(); __syncthreads(); }
    }

    // reduce across the 4 threads sharing each row
#pragma unroll
    for (int mt = 0; mt < 2; mt++)
#pragma unroll
        for (int h = 0; h < 2; h++) {
            s[mt][h] += __shfl_xor_sync(0xffffffffu, s[mt][h], 1);
            s[mt][h] += __shfl_xor_sync(0xffffffffu, s[mt][h], 2);
        }
    if ((lane & 3) == 0) {
        const float wbv = wb[0];
#pragma unroll
        for (int mt = 0; mt < 2; mt++)
#pragma unroll
            for (int h = 0; h < 2; h++) {
                long row = row0 + warp * 32 + mt * 16 + (lane >> 2) + 8 * h;
                if (row < N) {
                    float e = expf(s[mt][h] + wbv);
                    g_A[row] = e;
                    atomicAdd(&g_segsum[seg[row]], e);
                }
            }
    }
}

// ---------------------------------------------------------------------------
// Kernel 2: zero output + segment sums
// ---------------------------------------------------------------------------
__global__ void init_kernel(float* __restrict__ out, int bf, int B) {
    int i = blockIdx.x * blockDim.x + threadIdx.x;
    if (i < bf) out[i] = 0.f;
    if (i < B) g_segsum[i] = 0.f;
}

// ---------------------------------------------------------------------------
// Kernel 3: weighted segment-sum pooling.
// 256 threads: two independent 128-row run-length groups per block.
// ---------------------------------------------------------------------------
__global__ void __launch_bounds__(PTHR)
pool_kernel(const float* __restrict__ x, const int* __restrict__ seg,
            float* __restrict__ out, int N)
{
    __shared__ int   ss[RPB];
    __shared__ float wA[RPB];
    const int r0 = blockIdx.x * RPB;
    if (r0 >= N) return;
    const int cnt = min(RPB, N - r0);

    for (int r = threadIdx.x; r < cnt; r += PTHR) {
        int sgi = seg[r0 + r];
        ss[r] = sgi;
        wA[r] = g_A[r0 + r] / (g_segsum[sgi] + 1e-9f);
    }
    __syncthreads();

    const int grp  = threadIdx.x >> 7;          // row-group 0 or 1
    const int t    = threadIdx.x & 127;          // column
    const int rbeg = grp * 128;
    const int rend = min(cnt, rbeg + 128);
    if (rbeg >= cnt) return;

    const float* xp = x + (size_t)(r0 + rbeg) * F_DIM + t;
    float acc = 0.f;
    int cur = ss[rbeg];
#pragma unroll 4
    for (int r = rbeg; r < rend; r++) {
        const float xv = *xp;
        xp += F_DIM;
        const int sgi = ss[r];
        if (sgi != cur) {
            atomicAdd(out + (size_t)cur * F_DIM + t, acc);
            acc = 0.f;
            cur = sgi;
        }
        acc += wA[r] * xv;
    }
    atomicAdd(out + (size_t)cur * F_DIM + t, acc);
}

// ---------------------------------------------------------------------------
extern "C" void kernel_launch(void* const* d_in, const int* in_sizes, int n_in,
                              void* d_out, int out_size)
{
    const float* x   = (const float*)d_in[0];
    const int*   seg = (const int*)d_in[1];
    int base = (n_in >= 9) ? 3 : 2;
    const float* Vw = (const float*)d_in[base + 0];
    const float* Vb = (const float*)d_in[base + 1];
    const float* Uw = (const float*)d_in[base + 2];
    const float* Ub = (const float*)d_in[base + 3];
    const float* ww = (const float*)d_in[base + 4];
    const float* wb = (const float*)d_in[base + 5];

    int N = in_sizes[0] / F_DIM;
    int B = out_size / F_DIM;
    float* out = (float*)d_out;

    cudaFuncSetAttribute(score_kernel, cudaFuncAttributeMaxDynamicSharedMemorySize, SMEM_SZ);

    prep_kernel<<<128, 256>>>(Vw, Vb, Uw, Ub, ww);
    init_kernel<<<(out_size + 255) / 256, 256>>>(out, out_size, B);
    score_kernel<<<(N + BM - 1) / BM, 256, SMEM_SZ>>>(x, seg, wb, N);
    pool_kernel<<<(N + RPB - 1) / RPB, PTHR>>>(x, seg, out, N);
}

// round 6
// speedup vs baseline: 2.9153x; 1.1439x over previous
#include <cuda_runtime.h>
#include <cuda_fp16.h>
#include <math_constants.h>
#include <cstdint>

#define F_DIM 128
#define BM    256      // rows per score block

// device-global scratch (no allocation allowed)
__device__ float  g_segsum[8192];
__device__ float  g_pool[8192 * 128];  // unnormalized pooled numerators
__device__ __half g_wf[512 * 128];     // fp16 weights: rows 0-255 = Vw, 256-511 = Uw
__device__ float4 g_tab[256];          // {Vb, Ub, ww, 0} per a-dim

// ---------------------------------------------------------------------------
__device__ __forceinline__ uint32_t smem_u32(const void* p) {
    uint32_t a;
    asm("{ .reg .u64 t; cvta.to.shared.u64 t, %1; cvt.u32.u64 %0, t; }" : "=r"(a) : "l"(p));
    return a;
}
__device__ __forceinline__ float tanh_ap(float x) {
    float y; asm("tanh.approx.f32 %0, %1;" : "=f"(y) : "f"(x)); return y;
}
__device__ __forceinline__ void ldsm4(uint32_t* r, uint32_t a) {
    asm volatile("ldmatrix.sync.aligned.m8n8.x4.shared.b16 {%0,%1,%2,%3}, [%4];"
                 : "=r"(r[0]), "=r"(r[1]), "=r"(r[2]), "=r"(r[3]) : "r"(a));
}
__device__ __forceinline__ void mma16816(float* c, const uint32_t* a, uint32_t b0, uint32_t b1) {
    asm volatile("mma.sync.aligned.m16n8k16.row.col.f32.f16.f16.f32 "
                 "{%0,%1,%2,%3},{%4,%5,%6,%7},{%8,%9},{%0,%1,%2,%3};"
                 : "+f"(c[0]), "+f"(c[1]), "+f"(c[2]), "+f"(c[3])
                 : "r"(a[0]), "r"(a[1]), "r"(a[2]), "r"(a[3]), "r"(b0), "r"(b1));
}
__device__ __forceinline__ void cpa16(uint32_t dst, const void* src) {
    asm volatile("cp.async.cg.shared.global [%0], [%1], 16;" :: "r"(dst), "l"(src));
}
__device__ __forceinline__ void cpa_commit() { asm volatile("cp.async.commit_group;"); }
__device__ __forceinline__ void cpa_wait0()  { asm volatile("cp.async.wait_group 0;"); }

// smem layout constants (bytes)
#define XS_OFF   0            // x tile: 256 rows x 256B (128 fp16) swizzled = 64KB
#define WS_OFF   65536        // weights: 2 bufs x (64 rows x 256B) = 32KB
#define WS_SZ    16384
#define TAB_OFF  98304        // 256 x float4 = 4KB
#define SE_OFF   102400       // 256 floats: per-row exp scores
#define SS_OFF   103424       // 256 ints: per-row segment ids
#define SMEM_SZ  104448

// ---------------------------------------------------------------------------
// Kernel 0: one-time weight conversion + table build
// ---------------------------------------------------------------------------
__global__ void prep_kernel(const float* __restrict__ Vw, const float* __restrict__ Vb,
                            const float* __restrict__ Uw, const float* __restrict__ Ub,
                            const float* __restrict__ ww) {
    int i = blockIdx.x * blockDim.x + threadIdx.x;
    if (i < 32768) {
        g_wf[i]         = __float2half(Vw[i]);
        g_wf[32768 + i] = __float2half(Uw[i]);
    }
    if (i < 256) g_tab[i] = make_float4(Vb[i], Ub[i], ww[i], 0.f);
}

// ---------------------------------------------------------------------------
// Kernel 1: fully fused score + exp + segment-sum + weighted pooling.
// ---------------------------------------------------------------------------
__global__ void __launch_bounds__(256, 2)
score_kernel(const float* __restrict__ x, const int* __restrict__ seg,
             const float* __restrict__ wb, int N)
{
    extern __shared__ char sm[];
    const uint32_t sb  = smem_u32(sm);
    const uint32_t xsb = sb + XS_OFF;
    const uint32_t wsb = sb + WS_OFF;
    float4* tab = reinterpret_cast<float4*>(sm + TAB_OFF);
    float*  sE  = reinterpret_cast<float*>(sm + SE_OFF);
    int*    sS  = reinterpret_cast<int*>(sm + SS_OFF);

    const int tid  = threadIdx.x;
    const int warp = tid >> 5;
    const int lane = tid & 31;
    const int lh   = lane >> 4;
    const int l15  = lane & 15;
    const long row0 = (long)blockIdx.x * BM;

    // table + segment ids -> smem
    tab[tid] = g_tab[tid];
    {
        long gr = row0 + tid;
        sS[tid] = (gr < N) ? seg[gr] : 0;
    }

    // prefetch weights chunk 0 into buffer 0
    {
#pragma unroll
        for (int j = 0; j < 4; j++) {
            int i = tid + j * 256;
            int r = i >> 4, c16 = i & 15;
            int n = (r < 32) ? r : 256 + (r - 32);
            cpa16(wsb + r * 256 + (((c16 ^ (r & 7)) << 4)),
                  g_wf + (size_t)n * 128 + c16 * 8);
        }
        cpa_commit();
    }

    // load x tile (f32 -> fp16, swizzled)
#pragma unroll 4
    for (int i = tid; i < 4096; i += 256) {
        int r = i >> 4, c16 = i & 15;
        long gr = row0 + r;
        float4 v0 = make_float4(0.f, 0.f, 0.f, 0.f), v1 = v0;
        if (gr < N) {
            const float4* gp = reinterpret_cast<const float4*>(x + gr * 128 + c16 * 8);
            v0 = gp[0]; v1 = gp[1];
        }
        __half2 h0 = __floats2half2_rn(v0.x, v0.y);
        __half2 h1 = __floats2half2_rn(v0.z, v0.w);
        __half2 h2 = __floats2half2_rn(v1.x, v1.y);
        __half2 h3 = __floats2half2_rn(v1.z, v1.w);
        uint4 o;
        o.x = *reinterpret_cast<uint32_t*>(&h0);
        o.y = *reinterpret_cast<uint32_t*>(&h1);
        o.z = *reinterpret_cast<uint32_t*>(&h2);
        o.w = *reinterpret_cast<uint32_t*>(&h3);
        *reinterpret_cast<uint4*>(sm + XS_OFF + r * 256 + (((c16 ^ (r & 7)) << 4))) = o;
    }
    cpa_wait0();
    __syncthreads();

    const uint32_t rbA0 = xsb + (uint32_t)(warp * 32 + l15) * 256;
    const uint32_t rbA1 = rbA0 + 16 * 256;
    const uint32_t rbV0 = wsb + (uint32_t)l15 * 256;
    const uint32_t rbV1 = rbV0 + 16 * 256;
    const uint32_t rbU0 = rbV0 + 32 * 256;
    const uint32_t rbU1 = rbV1 + 32 * 256;

    float s[2][2] = {{0.f, 0.f}, {0.f, 0.f}};

    for (int ci = 0; ci < 8; ci++) {
        const int b = ci & 1;
        const uint32_t wofs = (uint32_t)b * WS_SZ;

        if (ci < 7) {
            const int nb2 = (ci + 1) * 32;
            const uint32_t dofs = (uint32_t)(b ^ 1) * WS_SZ;
#pragma unroll
            for (int j = 0; j < 4; j++) {
                int i = tid + j * 256;
                int r = i >> 4, c16 = i & 15;
                int n = (r < 32) ? nb2 + r : 256 + nb2 + (r - 32);
                cpa16(wsb + dofs + r * 256 + (((c16 ^ (r & 7)) << 4)),
                      g_wf + (size_t)n * 128 + c16 * 8);
            }
            cpa_commit();
        }

        float accV[2][4][4], accU[2][4][4];
#pragma unroll
        for (int mt = 0; mt < 2; mt++)
#pragma unroll
            for (int nt = 0; nt < 4; nt++)
#pragma unroll
                for (int p = 0; p < 4; p++) { accV[mt][nt][p] = 0.f; accU[mt][nt][p] = 0.f; }

#pragma unroll
        for (int ks = 0; ks < 8; ks++) {
            const uint32_t coff = (uint32_t)(((2 * ks + lh) ^ (lane & 7)) << 4);
            uint32_t a0[4], a1[4], bv0[4], bv1[4], bu0[4], bu1[4];
            ldsm4(a0,  rbA0 + coff);
            ldsm4(a1,  rbA1 + coff);
            ldsm4(bv0, rbV0 + wofs + coff);
            ldsm4(bv1, rbV1 + wofs + coff);
            ldsm4(bu0, rbU0 + wofs + coff);
            ldsm4(bu1, rbU1 + wofs + coff);
            mma16816(accV[0][0], a0, bv0[0], bv0[2]);
            mma16816(accV[0][1], a0, bv0[1], bv0[3]);
            mma16816(accV[0][2], a0, bv1[0], bv1[2]);
            mma16816(accV[0][3], a0, bv1[1], bv1[3]);
            mma16816(accV[1][0], a1, bv0[0], bv0[2]);
            mma16816(accV[1][1], a1, bv0[1], bv0[3]);
            mma16816(accV[1][2], a1, bv1[0], bv1[2]);
            mma16816(accV[1][3], a1, bv1[1], bv1[3]);
            mma16816(accU[0][0], a0, bu0[0], bu0[2]);
            mma16816(accU[0][1], a0, bu0[1], bu0[3]);
            mma16816(accU[0][2], a0, bu1[0], bu1[2]);
            mma16816(accU[0][3], a0, bu1[1], bu1[3]);
            mma16816(accU[1][0], a1, bu0[0], bu0[2]);
            mma16816(accU[1][1], a1, bu0[1], bu0[3]);
            mma16816(accU[1][2], a1, bu1[0], bu1[2]);
            mma16816(accU[1][3], a1, bu1[1], bu1[3]);
        }

        const float4* tb = tab + ci * 32;
#pragma unroll
        for (int mt = 0; mt < 2; mt++)
#pragma unroll
            for (int nt = 0; nt < 4; nt++)
#pragma unroll
                for (int p2 = 0; p2 < 2; p2++) {
                    const int nl = nt * 8 + (lane & 3) * 2 + p2;
                    const float4 pr = tb[nl];
#pragma unroll
                    for (int h = 0; h < 2; h++) {
                        const int p = p2 + 2 * h;
                        float v = accV[mt][nt][p] + pr.x;
                        float u = accU[mt][nt][p] + pr.y;
                        float g = tanh_ap(v) * (0.5f + 0.5f * tanh_ap(0.5f * u));
                        s[mt][h] += g * pr.z;
                    }
                }

        if (ci < 7) { cpa_wait0(); __syncthreads(); }
    }

    // reduce across the 4 threads sharing each row
#pragma unroll
    for (int mt = 0; mt < 2; mt++)
#pragma unroll
        for (int h = 0; h < 2; h++) {
            s[mt][h] += __shfl_xor_sync(0xffffffffu, s[mt][h], 1);
            s[mt][h] += __shfl_xor_sync(0xffffffffu, s[mt][h], 2);
        }
    if ((lane & 3) == 0) {
        const float wbv = wb[0];
#pragma unroll
        for (int mt = 0; mt < 2; mt++)
#pragma unroll
            for (int h = 0; h < 2; h++) {
                const int local = warp * 32 + mt * 16 + 8 * h + (lane >> 2);
                const long row = row0 + local;
                float e = 0.f;
                if (row < N) {
                    e = expf(s[mt][h] + wbv);
                    atomicAdd(&g_segsum[sS[local]], e);
                }
                sE[local] = e;
            }
    }
    __syncthreads();

    // ---------------- fused pooling from the live SMEM x tile ----------------
    // 4 row-groups of 64 rows; 64 column-pair threads per group (half2 each).
    {
        const int grp  = tid >> 6;          // 0..3
        const int tc   = tid & 63;          // column pair: cols 2tc, 2tc+1
        const int rbeg = grp * 64;
        const uint32_t cbyte = (uint32_t)((tc & 3) << 2);
        const int c16 = tc >> 2;

        float a0 = 0.f, a1 = 0.f;
        int cur = sS[rbeg];
#pragma unroll 4
        for (int rr = 0; rr < 64; rr++) {
            const int r = rbeg + rr;
            const uint32_t addr = xsb + (uint32_t)r * 256 +
                                  (uint32_t)(((c16 ^ (r & 7)) << 4)) + cbyte;
            uint32_t raw;
            asm("ld.shared.b32 %0, [%1];" : "=r"(raw) : "r"(addr));
            const __half2 h2 = *reinterpret_cast<__half2*>(&raw);
            const float2 xv = __half22float2(h2);
            const int sgi = sS[r];
            if (sgi != cur) {
                atomicAdd(&g_pool[(size_t)cur * F_DIM + 2 * tc],     a0);
                atomicAdd(&g_pool[(size_t)cur * F_DIM + 2 * tc + 1], a1);
                a0 = 0.f; a1 = 0.f; cur = sgi;
            }
            const float w = sE[r];
            a0 = fmaf(w, xv.x, a0);
            a1 = fmaf(w, xv.y, a1);
        }
        atomicAdd(&g_pool[(size_t)cur * F_DIM + 2 * tc],     a0);
        atomicAdd(&g_pool[(size_t)cur * F_DIM + 2 * tc + 1], a1);
    }
}

// ---------------------------------------------------------------------------
// Kernel 2: zero pooled numerators + segment sums
// ---------------------------------------------------------------------------
__global__ void init_kernel(int bf, int B) {
    int i = blockIdx.x * blockDim.x + threadIdx.x;
    if (i < bf) g_pool[i] = 0.f;
    if (i < B) g_segsum[i] = 0.f;
}

// ---------------------------------------------------------------------------
// Kernel 3: normalize into output
// ---------------------------------------------------------------------------
__global__ void finalize_kernel(float* __restrict__ out, int total) {
    int i = blockIdx.x * blockDim.x + threadIdx.x;
    if (i < total) out[i] = g_pool[i] / (g_segsum[i >> 7] + 1e-9f);
}

// ---------------------------------------------------------------------------
extern "C" void kernel_launch(void* const* d_in, const int* in_sizes, int n_in,
                              void* d_out, int out_size)
{
    const float* x   = (const float*)d_in[0];
    const int*   seg = (const int*)d_in[1];
    int base = (n_in >= 9) ? 3 : 2;
    const float* Vw = (const float*)d_in[base + 0];
    const float* Vb = (const float*)d_in[base + 1];
    const float* Uw = (const float*)d_in[base + 2];
    const float* Ub = (const float*)d_in[base + 3];
    const float* ww = (const float*)d_in[base + 4];
    const float* wb = (const float*)d_in[base + 5];

    int N = in_sizes[0] / F_DIM;
    int B = out_size / F_DIM;
    float* out = (float*)d_out;

    cudaFuncSetAttribute(score_kernel, cudaFuncAttributeMaxDynamicSharedMemorySize, SMEM_SZ);

    prep_kernel<<<128, 256>>>(Vw, Vb, Uw, Ub, ww);
    init_kernel<<<(out_size + 255) / 256, 256>>>(out_size, B);
    score_kernel<<<(N + BM - 1) / BM, 256, SMEM_SZ>>>(x, seg, wb, N);
    finalize_kernel<<<(out_size + 255) / 256, 256>>>(out, out_size);
}